// round 1
// baseline (speedup 1.0000x reference)
#include <cuda_runtime.h>

#define B_ 2
#define F_ 128
#define N_ 192
#define S_ 192
#define H_ 4
#define D_ 64
#define HD_ 256
#define CH 48
#define NCH 4
#define LOG2E 1.4426950408889634f

static __device__ float d_SS[B_*H_*N_*S_];   // [b][h][i][s]  = log2e*(s_src + q_src)
static __device__ float d_SD[B_*H_*S_*N_];   // [b][h][s][j]  = log2e*(s_dst + q_dst)
static __device__ float d_P[F_*8];           // [f][which*4+h], scaled by log2e
static __device__ float d_Q[8];              // [which*4+h],   scaled by log2e
static __device__ float d_colsum[B_*F_];
static __device__ float d_sumg[HD_];

__device__ __forceinline__ float ex2f(float x){ float r; asm("ex2.approx.ftz.f32 %0, %1;" : "=f"(r) : "f"(x)); return r; }
__device__ __forceinline__ float rcpf(float x){ float r; asm("rcp.approx.ftz.f32 %0, %1;" : "=f"(r) : "f"(x)); return r; }

// Fold W_attn into W_lin/b_lin: P[f][which*4+h], Q[which*4+h]; pre-scale by log2(e).
__global__ void k_prep(const float* __restrict__ Wl, const float* __restrict__ bl,
                       const float* __restrict__ Wa){
    int t = threadIdx.x;
    if (t < 512){
        int f = t >> 2, h = t & 3;
        float ps = 0.f, pd = 0.f;
        #pragma unroll 8
        for (int d = 0; d < D_; ++d){
            float wl = Wl[f*HD_ + h*D_ + d];
            ps += wl * Wa[d];
            pd += wl * Wa[D_ + d];
        }
        d_P[f*8 + h]     = ps * LOG2E;
        d_P[f*8 + 4 + h] = pd * LOG2E;
    }
    if (t < 8){
        int which = t >> 2, h = t & 3;
        float q = 0.f;
        for (int d = 0; d < D_; ++d) q += bl[h*D_ + d] * Wa[which*D_ + d];
        d_Q[which*4 + h] = q * LOG2E;
    }
}

// colsum over (n,s) for each (b,f)
__global__ void k_colsum(const float* __restrict__ X){
    int bf = blockIdx.x;
    const float* p = X + (size_t)bf * (N_*S_);
    float acc = 0.f;
    for (int i = threadIdx.x; i < N_*S_; i += 256) acc += p[i];
    __shared__ float sh[256];
    sh[threadIdx.x] = acc; __syncthreads();
    for (int o = 128; o > 0; o >>= 1){
        if (threadIdx.x < o) sh[threadIdx.x] += sh[threadIdx.x + o];
        __syncthreads();
    }
    if (threadIdx.x == 0) d_colsum[bf] = sh[0];
}

// sum_g[c] = colsumX · W_lin[:,c] + R*b_lin[c]
__global__ void k_sumg(const float* __restrict__ Wl, const float* __restrict__ bl){
    int c = threadIdx.x;
    float acc = (float)(B_*N_*S_) * bl[c];
    for (int f = 0; f < F_; ++f)
        acc += (d_colsum[f] + d_colsum[F_ + f]) * Wl[f*HD_ + c];
    d_sumg[c] = acc;
}

// Projection: SS[b][h][n][s], SD[b][h][s][n] from X via 128->8 GEMV
__global__ void __launch_bounds__(192) k_proj(const float* __restrict__ X){
    __shared__ float sP[F_*8];
    __shared__ float sQ[8];
    int b = blockIdx.x / N_, n = blockIdx.x % N_;
    int t = threadIdx.x;
    for (int i = t; i < F_*8; i += 192) sP[i] = d_P[i];
    if (t < 8) sQ[t] = d_Q[t];
    __syncthreads();
    float acc[8];
    #pragma unroll
    for (int k = 0; k < 8; ++k) acc[k] = 0.f;
    const float* xp = X + ((size_t)(b*F_)*N_ + n)*S_ + t;
    #pragma unroll 4
    for (int f = 0; f < F_; ++f){
        float x = xp[(size_t)f * (N_*S_)];
        float4 p0 = ((const float4*)sP)[f*2];
        float4 p1 = ((const float4*)sP)[f*2 + 1];
        acc[0] += x*p0.x; acc[1] += x*p0.y; acc[2] += x*p0.z; acc[3] += x*p0.w;
        acc[4] += x*p1.x; acc[5] += x*p1.y; acc[6] += x*p1.z; acc[7] += x*p1.w;
    }
    #pragma unroll
    for (int h = 0; h < H_; ++h){
        d_SS[((b*H_+h)*N_ + n)*S_ + t] = acc[h]   + sQ[h];
        d_SD[((b*H_+h)*S_ + t)*N_ + n] = acc[4+h] + sQ[4+h];
    }
}

// Main tile kernel: one CTA per (b,h,i); column-softmax over s, alpha[s]=sum_j E/Z, outer product with sum_g
__global__ void __launch_bounds__(192) k_attn(const int* __restrict__ A,
                                              const float* __restrict__ b_attn,
                                              float* __restrict__ out){
    __shared__ float E[S_][CH+1];   // exp tile, stride 49 (odd -> conflict-free both ways)
    __shared__ float w[S_];
    __shared__ float Zp[4][CH];
    __shared__ float invZ[CH];
    __shared__ float sg[D_];
    int i = blockIdx.x, h = blockIdx.y, b = blockIdx.z;
    int t = threadIdx.x;
    float bK = __ldg(b_attn) * LOG2E;
    {
        float ssv = d_SS[((b*H_+h)*N_ + i)*S_ + t];
        int av = A[t*N_ + i];
        w[t] = av ? (ssv + bK) : -1e30f;   // masked row -> exp underflows to 0
    }
    if (t < D_) sg[t] = d_sumg[h*D_ + t];
    __syncthreads();

    const float* V = d_SD + (size_t)(b*H_+h)*S_*N_;
    int jl  = t % CH;
    int sgp = t / CH;
    int s0  = sgp * CH;
    float alpha = 0.f;

    for (int jc = 0; jc < NCH; ++jc){
        int j = jc*CH + jl;
        float z = 0.f;
        #pragma unroll 8
        for (int k = 0; k < CH; ++k){
            int s = s0 + k;
            float a = w[s] + V[s*N_ + j];          // already log2e-scaled
            float e = ex2f(fmaxf(a, 0.2f*a));       // leakyrelu commutes with positive scale
            E[s][jl] = e;
            z += e;
        }
        Zp[sgp][jl] = z;
        __syncthreads();
        if (t < CH){
            float Z = Zp[0][t] + Zp[1][t] + Zp[2][t] + Zp[3][t];
            invZ[t] = (Z > 0.f) ? rcpf(Z) : 0.f;    // all-masked column -> NaN->0 semantics
        }
        __syncthreads();
        float acc = 0.f;
        #pragma unroll 8
        for (int q = 0; q < CH; ++q) acc += E[t][q] * invZ[q];
        alpha += acc;
        __syncthreads();                            // protect E before next chunk
    }

    float* op = out + ((size_t)(b*HD_ + h*D_)*N_ + i)*S_ + t;
    #pragma unroll 4
    for (int d = 0; d < D_; ++d) op[(size_t)d * (N_*S_)] = alpha * sg[d];
}

extern "C" void kernel_launch(void* const* d_in, const int* in_sizes, int n_in,
                              void* d_out, int out_size){
    const float* X  = (const float*)d_in[0];
    const int*   A  = (const int*)  d_in[1];
    const float* Wl = (const float*)d_in[2];
    const float* bl = (const float*)d_in[3];
    const float* Wa = (const float*)d_in[4];
    const float* ba = (const float*)d_in[5];
    float* out = (float*)d_out;

    k_prep  <<<1, 512>>>(Wl, bl, Wa);
    k_colsum<<<B_*F_, 256>>>(X);
    k_sumg  <<<1, HD_>>>(Wl, bl);
    k_proj  <<<B_*N_, 192>>>(X);
    dim3 g(N_, H_, B_);
    k_attn  <<<g, 192>>>(A, ba, out);
}